// round 9
// baseline (speedup 1.0000x reference)
#include <cuda_runtime.h>
#include <cuda_bf16.h>
#include <cuda_fp16.h>
#include <cstdint>
#include <math.h>

// ---------------------------------------------------------------------------
// EfficientMoEMLPBlock — expert-choice MoE MLP on sm_103 (portable PTX only).
//   E=48, S=4, D=1024, M=1024, K=D/S=256, T=16384, cap=512
// Round 8: CTA 128x256, warp tile 64x64 (LDSM-pressure fix, MMA-bound now).
//          GEMM1: y=(Ah+Al)·Bf (2-term).  GEMM2: y=hf·Bf (1-term, h rounded).
// ---------------------------------------------------------------------------

#define T_TOK   16384
#define D_DIM   1024
#define E_EXP   48
#define S_SHARD 4
#define M_DIM   1024
#define K_DIM   256
#define CAP     512

typedef unsigned int uint32;
typedef unsigned long long uint64;

// ------------------------- scratch (device globals) ------------------------
__device__ float g_logits[(size_t)E_EXP * T_TOK];
__device__ int   g_idx[E_EXP * CAP];
__device__ float g_w[E_EXP * CAP];
__device__ __half g_xgh[(size_t)E_EXP * CAP * D_DIM];
__device__ __half g_xgl[(size_t)E_EXP * CAP * D_DIM];
__device__ __half g_w1h[(size_t)E_EXP * S_SHARD * M_DIM * D_DIM];  // [es][m][d]
__device__ __half g_w2h[(size_t)E_EXP * S_SHARD * K_DIM * M_DIM];  // [es][k][m]
__device__ __half g_hh[(size_t)E_EXP * S_SHARD * CAP * M_DIM];     // [es][c][m]

// ------------------------------- helpers -----------------------------------
__device__ __forceinline__ unsigned fkey(float f) {
    unsigned u = __float_as_uint(f);
    return (u & 0x80000000u) ? ~u : (u | 0x80000000u);
}
__device__ __forceinline__ float gelu_f(float v) {
    return 0.5f * v * (1.0f + erff(v * 0.70710678118654752440f));
}
__device__ __forceinline__ uint32 pack_hf(__half a, __half b) {
    return (uint32)__half_as_ushort(a) | ((uint32)__half_as_ushort(b) << 16);
}
__device__ __forceinline__ void split_hf(float v, __half& h, __half& l) {
    h = __float2half_rn(v);
    l = __float2half_rn(v - __half2float(h));
}
__device__ __forceinline__ uint32 smem_u32(const void* p) {
    uint32 a;
    asm("{ .reg .u64 t; cvta.to.shared.u64 t, %1; cvt.u32.u64 %0, t; }" : "=r"(a) : "l"(p));
    return a;
}
// packed-swizzle smem layout: 2 logical rows (64B each) per 128B physical row;
// 16B chunks XOR-swizzled so 8 consecutive rows at fixed chunk are conflict-free.
__device__ __forceinline__ int phys(int r, int c) {
    return ((r >> 1) << 7) + (((((r & 1) << 2) | c) ^ ((r >> 1) & 7)) << 4);
}
__device__ __forceinline__ void cp_async16(uint32 saddr, const void* gaddr) {
    asm volatile("cp.async.cg.shared.global [%0], [%1], 16;"
                 :: "r"(saddr), "l"(gaddr) : "memory");
}
#define CP_COMMIT() asm volatile("cp.async.commit_group;" ::: "memory")
#define CP_WAIT(n)  asm volatile("cp.async.wait_group %0;" :: "n"(n) : "memory")

__device__ __forceinline__ void ldsm4(uint32* r, uint32 addr) {
    asm volatile("ldmatrix.sync.aligned.m8n8.x4.shared.b16 {%0,%1,%2,%3}, [%4];"
                 : "=r"(r[0]), "=r"(r[1]), "=r"(r[2]), "=r"(r[3]) : "r"(addr));
}
__device__ __forceinline__ void mma16816(float* c, const uint32* a, const uint32* b) {
    asm volatile(
        "mma.sync.aligned.m16n8k16.row.col.f32.f16.f16.f32 "
        "{%0,%1,%2,%3}, {%4,%5,%6,%7}, {%8,%9}, {%0,%1,%2,%3};"
        : "+f"(c[0]), "+f"(c[1]), "+f"(c[2]), "+f"(c[3])
        : "r"(a[0]), "r"(a[1]), "r"(a[2]), "r"(a[3]), "r"(b[0]), "r"(b[1]));
}
#define FENCE_ASYNC() asm volatile("fence.proxy.async.shared::cta;" ::: "memory")

// ------------------------------ zero out -----------------------------------
__global__ void zero_kernel(float4* __restrict__ p, int n4) {
    int i = blockIdx.x * blockDim.x + threadIdx.x;
    if (i < n4) p[i] = make_float4(0.f, 0.f, 0.f, 0.f);
}

// ------------------------- router logits [E][T] ----------------------------
__global__ __launch_bounds__(256) void router_kernel(const float* __restrict__ x,
                                                     const float* __restrict__ Wr) {
    __shared__ float xs[32][129];
    __shared__ float ws[32][49];
    const int tid = threadIdx.x;
    const int tb  = blockIdx.x * 128;
    const int t0  = (tid & 31) * 4;
    const int e0  = (tid >> 5) * 6;

    float acc[4][6];
#pragma unroll
    for (int i = 0; i < 4; i++)
#pragma unroll
        for (int j = 0; j < 6; j++) acc[i][j] = 0.f;

    for (int kb = 0; kb < D_DIM; kb += 32) {
        __syncthreads();
        for (int i = tid; i < 128 * 32; i += 256) {
            int r = i >> 5, c = i & 31;
            xs[c][r] = x[(size_t)(tb + r) * D_DIM + kb + c];
        }
        for (int i = tid; i < E_EXP * 32; i += 256) {
            int r = i >> 5, c = i & 31;
            ws[c][r] = Wr[(size_t)r * D_DIM + kb + c];
        }
        __syncthreads();
#pragma unroll 8
        for (int kk = 0; kk < 32; kk++) {
            float xv[4], wv[6];
#pragma unroll
            for (int i = 0; i < 4; i++) xv[i] = xs[kk][t0 + i];
#pragma unroll
            for (int j = 0; j < 6; j++) wv[j] = ws[kk][e0 + j];
#pragma unroll
            for (int i = 0; i < 4; i++)
#pragma unroll
                for (int j = 0; j < 6; j++) acc[i][j] += xv[i] * wv[j];
        }
    }
#pragma unroll
    for (int j = 0; j < 6; j++)
#pragma unroll
        for (int i = 0; i < 4; i++)
            g_logits[(size_t)(e0 + j) * T_TOK + tb + t0 + i] = acc[i][j];
}

// -------------------- per-expert top-512 + softmax --------------------------
__global__ __launch_bounds__(256) void topk_kernel() {
    const int e = blockIdx.x;
    const float* lg = g_logits + (size_t)e * T_TOK;
    const int tid = threadIdx.x;

    __shared__ unsigned hist[4096];
    __shared__ unsigned csum[256];
    __shared__ int      eq_idx[256];
    __shared__ float    svals[CAP];
    __shared__ float    sred[256];
    __shared__ unsigned s_binA, s_cntA, s_binB, s_cntB, s_key;
    __shared__ unsigned s_pos, s_eqcnt;

    for (int i = tid; i < 4096; i += 256) hist[i] = 0;
    __syncthreads();
    for (int t = tid; t < T_TOK; t += 256) {
        unsigned k = fkey(lg[t]);
        atomicAdd(&hist[k >> 20], 1u);
    }
    __syncthreads();
    {
        unsigned s = 0;
#pragma unroll
        for (int j = 0; j < 16; j++) s += hist[tid * 16 + j];
        csum[tid] = s;
    }
    __syncthreads();
    if (tid == 0) {
        unsigned need = CAP, cum = 0;
        int chunk = 0;
        for (int c = 255; c >= 0; c--) {
            if (cum + csum[c] >= need) { chunk = c; break; }
            cum += csum[c];
        }
        int bsel = chunk * 16;
        for (int b = chunk * 16 + 15; b >= chunk * 16; b--) {
            if (cum + hist[b] >= need) { bsel = b; break; }
            cum += hist[b];
        }
        s_binA = (unsigned)bsel;
        s_cntA = cum;
    }
    __syncthreads();
    const unsigned binA = s_binA, cntA = s_cntA;

    for (int i = tid; i < 4096; i += 256) hist[i] = 0;
    __syncthreads();
    for (int t = tid; t < T_TOK; t += 256) {
        unsigned k = fkey(lg[t]);
        if ((k >> 20) == binA) atomicAdd(&hist[(k >> 8) & 0xFFFu], 1u);
    }
    __syncthreads();
    {
        unsigned s = 0;
#pragma unroll
        for (int j = 0; j < 16; j++) s += hist[tid * 16 + j];
        csum[tid] = s;
    }
    __syncthreads();
    if (tid == 0) {
        unsigned need = CAP - cntA, cum = 0;
        int chunk = 0;
        for (int c = 255; c >= 0; c--) {
            if (cum + csum[c] >= need) { chunk = c; break; }
            cum += csum[c];
        }
        int bsel = chunk * 16;
        for (int b = chunk * 16 + 15; b >= chunk * 16; b--) {
            if (cum + hist[b] >= need) { bsel = b; break; }
            cum += hist[b];
        }
        s_binB = (unsigned)bsel;
        s_cntB = cum;
    }
    __syncthreads();
    const unsigned binB = s_binB, cntB = s_cntB;
    const unsigned prefix = (binA << 12) | binB;

    for (int i = tid; i < 256; i += 256) hist[i] = 0;
    __syncthreads();
    for (int t = tid; t < T_TOK; t += 256) {
        unsigned k = fkey(lg[t]);
        if ((k >> 8) == prefix) atomicAdd(&hist[k & 0xFFu], 1u);
    }
    __syncthreads();
    if (tid == 0) {
        unsigned need = CAP - cntA - cntB, cum = 0;
        int bsel = 0;
        for (int b = 255; b >= 0; b--) {
            if (cum + hist[b] >= need) { bsel = b; break; }
            cum += hist[b];
        }
        s_key = (prefix << 8) | (unsigned)bsel;
        s_pos = 0;
        s_eqcnt = 0;
    }
    __syncthreads();
    const unsigned ukey = s_key;

    for (int t = tid; t < T_TOK; t += 256) {
        float v = lg[t];
        unsigned k = fkey(v);
        if (k > ukey) {
            unsigned p = atomicAdd(&s_pos, 1u);
            g_idx[e * CAP + p] = t;
            svals[p] = v;
        } else if (k == ukey) {
            unsigned q = atomicAdd(&s_eqcnt, 1u);
            if (q < 256) eq_idx[q] = t;
        }
    }
    __syncthreads();
    if (tid == 0) {
        int ngt  = (int)s_pos;
        int need = CAP - ngt;
        int m    = (int)(s_eqcnt < 256u ? s_eqcnt : 256u);
        for (int i = 0; i < need; i++) {
            int best = 0x7fffffff, bj = -1;
            for (int j = 0; j < m; j++)
                if (eq_idx[j] < best) { best = eq_idx[j]; bj = j; }
            eq_idx[bj] = 0x7fffffff;
            g_idx[e * CAP + ngt + i] = best;
            svals[ngt + i] = lg[best];
        }
    }
    __syncthreads();

    float mx = -3.4e38f;
    for (int i = tid; i < CAP; i += 256) mx = fmaxf(mx, svals[i]);
    sred[tid] = mx;
    __syncthreads();
    for (int o = 128; o > 0; o >>= 1) {
        if (tid < o) sred[tid] = fmaxf(sred[tid], sred[tid + o]);
        __syncthreads();
    }
    const float vmax = sred[0];
    __syncthreads();
    float sum = 0.f;
    for (int i = tid; i < CAP; i += 256) sum += expf(svals[i] - vmax);
    sred[tid] = sum;
    __syncthreads();
    for (int o = 128; o > 0; o >>= 1) {
        if (tid < o) sred[tid] += sred[tid + o];
        __syncthreads();
    }
    const float tot = sred[0];
    __syncthreads();
    for (int i = tid; i < CAP; i += 256)
        g_w[e * CAP + i] = expf(svals[i] - vmax) / tot;
}

// --------------------- gather + fp16 hi/lo split ----------------------------
__global__ __launch_bounds__(256) void gather_kernel(const float* __restrict__ x) {
    const int ec = blockIdx.x;
    const int t  = g_idx[ec];
    float4 v = ((const float4*)(x + (size_t)t * D_DIM))[threadIdx.x];
    __half h0, h1, h2, h3, l0, l1, l2, l3;
    split_hf(v.x, h0, l0); split_hf(v.y, h1, l1);
    split_hf(v.z, h2, l2); split_hf(v.w, h3, l3);
    uint2 hh = make_uint2(pack_hf(h0, h1), pack_hf(h2, h3));
    uint2 ll = make_uint2(pack_hf(l0, l1), pack_hf(l2, l3));
    ((uint2*)(g_xgh + (size_t)ec * D_DIM))[threadIdx.x] = hh;
    ((uint2*)(g_xgl + (size_t)ec * D_DIM))[threadIdx.x] = ll;
}

// ---- fused weight transpose + fp16 round  [es][R][C] -> [es][C][R] ---------
__global__ __launch_bounds__(256) void conv_kernel(const float* __restrict__ W1,
                                                   const float* __restrict__ W2) {
    __shared__ float t[32][33];
    const bool is1 = blockIdx.x < 32;
    const int bx = is1 ? blockIdx.x : blockIdx.x - 32;
    const int es = blockIdx.z;
    const int C  = is1 ? 1024 : 256;
    const float* in = is1 ? W1 : W2;
    __half* outp = is1 ? g_w1h : g_w2h;

    const int c0 = bx * 32, r0 = blockIdx.y * 32;
    const int tx = threadIdx.x & 31, ty = threadIdx.x >> 5;
    const float* ip = in + (size_t)es * 1024 * C;
#pragma unroll
    for (int j = 0; j < 4; j++) {
        int r = ty + j * 8;
        t[r][tx] = ip[(size_t)(r0 + r) * C + c0 + tx];
    }
    __syncthreads();
    const size_t ob = (size_t)es * 1024 * C;
#pragma unroll
    for (int j = 0; j < 4; j++) {
        int rr = ty + j * 8;
        outp[ob + (size_t)(c0 + rr) * 1024 + r0 + tx] = __float2half_rn(t[tx][rr]);
    }
}

// -------------------- mma.sync fp16 GEMM, CTA 128x256 -----------------------
// 8 warps (2 x 4), warp tile 64x64, K=1024 in 32 chunks of 32.
// GEMM1 (ATERMS=2): stage = Ah|Al|Bf = 8+8+16 KB = 32KB, 3 stages = 96KB.
// GEMM2 (ATERMS=1): stage = Ah|Bf  = 8+16 KB = 24KB, 3 stages = 72KB;
//                   epilogue C tile 128x264 fp32 = 132KB (smem = 136KB).
#define NCK 32
#define SMEM_G1 (3 * 32768)
#define SMEM_G2 (128 * 264 * 4)

template <bool IS_G2>
__global__ __launch_bounds__(256, 1) void moe_mma(const float* __restrict__ bias_g,
                                                  float* __restrict__ out) {
    extern __shared__ char smem[];
    __shared__ float bias_s[256];
    const int ATERMS = IS_G2 ? 1 : 2;
    const int STG = IS_G2 ? 24576 : 32768;
    const int BOFF = IS_G2 ? 8192 : 16384;
    const int es   = blockIdx.z, e = es >> 2, s = es & 3;
    const int row0 = blockIdx.y * 128;
    const int col0 = blockIdx.x * 256;
    const int tid  = threadIdx.x;
    const int lane = tid & 31, wid = tid >> 5;
    const int warpM = wid >> 2, warpN = wid & 3;
    const uint32 sb = smem_u32(smem);

    const __half* Aph = (IS_G2 ? g_hh + (size_t)es * CAP * M_DIM
                               : g_xgh + (size_t)e * CAP * D_DIM) + (size_t)row0 * 1024;
    const __half* Apl = g_xgl + (size_t)e * CAP * D_DIM + (size_t)row0 * 1024; // G1 only
    const __half* Bpf = (IS_G2 ? g_w2h + (size_t)es * K_DIM * M_DIM
                               : g_w1h + (size_t)es * M_DIM * D_DIM) + (size_t)col0 * 1024;

    // per-thread cp.async slots:
    //  G1: 2048 chunks/stage -> 8 slots; G2: 1536 -> 6 slots
    const int NSLOT = IS_G2 ? 6 : 8;
    uint32 soff[8];
    const __half* gp[8];
#pragma unroll
    for (int i = 0; i < 8; i++) {
        if (i >= NSLOT) break;
        int idx = tid + i * 256;
        int na = ATERMS * 512;  // # A chunks per stage
        if (idx < na) {
            int plane = idx >> 9;
            int w = idx & 511;
            int r = w >> 2, c = w & 3;
            soff[i] = (uint32)(plane * 8192 + phys(r, c));
            gp[i] = (plane ? Apl : Aph) + r * 1024 + c * 8;
        } else {
            int w = idx - na;       // 0..1023 over 256 B rows
            int r = w >> 2, c = w & 3;
            soff[i] = (uint32)(BOFF + phys(r, c));
            gp[i] = Bpf + r * 1024 + c * 8;
        }
    }

    float acc[4][8][4];
#pragma unroll
    for (int mi = 0; mi < 4; mi++)
#pragma unroll
        for (int ni = 0; ni < 8; ni++)
#pragma unroll
            for (int q = 0; q < 4; q++) acc[mi][ni][q] = 0.f;

    // prologue: stages 0,1
#pragma unroll
    for (int st = 0; st < 2; st++) {
        const int kb = st * 32;
#pragma unroll
        for (int i = 0; i < 8; i++) {
            if (i >= NSLOT) break;
            cp_async16(sb + st * STG + soff[i], gp[i] + kb);
        }
        CP_COMMIT();
    }

    for (int ck = 0; ck < NCK; ck++) {
        CP_WAIT(1);
        __syncthreads();
        if (ck + 2 < NCK) {
            const int st = (ck + 2) % 3;
            const int kb = (ck + 2) * 32;
#pragma unroll
            for (int i = 0; i < 8; i++) {
                if (i >= NSLOT) break;
                cp_async16(sb + st * STG + soff[i], gp[i] + kb);
            }
        }
        CP_COMMIT();

        const uint32 s0 = sb + (ck % 3) * STG;
#pragma unroll
        for (int kh = 0; kh < 2; kh++) {
            uint32 Bf[4][4];
#pragma unroll
            for (int np = 0; np < 4; np++) {
                int nr = warpN * 64 + np * 16 + ((lane >> 4) << 3) + (lane & 7);
                int ch = kh * 2 + ((lane >> 3) & 1);
                ldsm4(Bf[np], s0 + BOFF + phys(nr, ch));
            }
#pragma unroll
            for (int mi = 0; mi < 4; mi++) {
                int ar = warpM * 64 + mi * 16 + (lane & 15);
                int ch = kh * 2 + (lane >> 4);
                int po = phys(ar, ch);
                uint32 Ah[4], Al[4];
                ldsm4(Ah, s0 + po);
                if (ATERMS == 2) ldsm4(Al, s0 + 8192 + po);
#pragma unroll
                for (int ni = 0; ni < 8; ni++) {
                    const uint32* bf = &Bf[ni >> 1][(ni & 1) * 2];
                    mma16816(acc[mi][ni], Ah, bf);
                    if (ATERMS == 2) mma16816(acc[mi][ni], Al, bf);
                }
            }
        }
    }

    CP_WAIT(0);
    __syncthreads();

    // ------------------------------ epilogue -------------------------------
    const int NB = IS_G2 ? K_DIM : M_DIM;
    if (tid < NB - col0 && tid < 256)
        bias_s[tid] = bias_g[(size_t)es * NB + col0 + tid];
    __syncthreads();

    if (!IS_G2) {
        // two passes over 128-col halves through a 128x132 smem tile
        float* Cs = (float*)smem;
        uint32* dh = (uint32*)g_hh;
        const size_t rowbase = (size_t)es * CAP + row0;
#pragma unroll
        for (int p = 0; p < 2; p++) {
            if ((warpN >> 1) == p) {
                const int wn = warpN & 1;  // 0..1 within half
#pragma unroll
                for (int mi = 0; mi < 4; mi++)
#pragma unroll
                    for (int ni = 0; ni < 8; ni++) {
                        int r0 = warpM * 64 + mi * 16 + (lane >> 2);
                        int c0 = wn * 64 + ni * 8 + (lane & 3) * 2;
                        Cs[r0 * 132 + c0]       = acc[mi][ni][0];
                        Cs[r0 * 132 + c0 + 1]   = acc[mi][ni][1];
                        Cs[(r0 + 8) * 132 + c0]     = acc[mi][ni][2];
                        Cs[(r0 + 8) * 132 + c0 + 1] = acc[mi][ni][3];
                    }
            }
            __syncthreads();
#pragma unroll 4
            for (int it = 0; it < 32; it++) {
                int idx = tid + it * 256;
                int r = idx >> 6, cp = idx & 63;
                int gc = p * 128 + cp * 2;
                float v0 = gelu_f(Cs[r * 132 + cp * 2]     + bias_s[gc]);
                float v1 = gelu_f(Cs[r * 132 + cp * 2 + 1] + bias_s[gc + 1]);
                dh[(rowbase + r) * 512 + (col0 >> 1) + p * 64 + cp] =
                    pack_hf(__float2half_rn(v0), __float2half_rn(v1));
            }
            __syncthreads();
        }
    } else {
        // full 128x256 C tile in smem (stride 264), then bulk reduce-add rows
        float* Cs = (float*)smem;
        float wv[8];
#pragma unroll
        for (int mi = 0; mi < 4; mi++) {
            wv[mi * 2]     = g_w[e * CAP + row0 + warpM * 64 + mi * 16 + (lane >> 2)];
            wv[mi * 2 + 1] = g_w[e * CAP + row0 + warpM * 64 + mi * 16 + (lane >> 2) + 8];
        }
#pragma unroll
        for (int mi = 0; mi < 4; mi++)
#pragma unroll
            for (int ni = 0; ni < 8; ni++) {
                int r0 = warpM * 64 + mi * 16 + (lane >> 2);
                int c0 = warpN * 64 + ni * 8 + (lane & 3) * 2;
                Cs[r0 * 264 + c0]       = (acc[mi][ni][0] + bias_s[c0])     * wv[mi * 2];
                Cs[r0 * 264 + c0 + 1]   = (acc[mi][ni][1] + bias_s[c0 + 1]) * wv[mi * 2];
                Cs[(r0 + 8) * 264 + c0]     = (acc[mi][ni][2] + bias_s[c0])     * wv[mi * 2 + 1];
                Cs[(r0 + 8) * 264 + c0 + 1] = (acc[mi][ni][3] + bias_s[c0 + 1]) * wv[mi * 2 + 1];
            }
        __syncthreads();
        FENCE_ASYNC();
        if (tid < 128) {
            const int r = tid;
            const int tok = g_idx[e * CAP + row0 + r];
            float* gdst = out + (size_t)tok * D_DIM + s * K_DIM;
            uint32 sa = sb + (uint32)r * 264 * 4;
            asm volatile(
                "cp.reduce.async.bulk.global.shared::cta.bulk_group.add.f32 [%0], [%1], %2;"
                :: "l"(gdst), "r"(sa), "r"(1024u) : "memory");
            asm volatile("cp.async.bulk.commit_group;" ::: "memory");
            asm volatile("cp.async.bulk.wait_group 0;" ::: "memory");
        }
        __syncthreads();
    }
}

// ------------------------------ launch -------------------------------------
extern "C" void kernel_launch(void* const* d_in, const int* in_sizes, int n_in,
                              void* d_out, int out_size) {
    const float* x  = (const float*)d_in[0];
    const float* Wr = (const float*)d_in[1];
    const float* W1 = (const float*)d_in[2];
    const float* b1 = (const float*)d_in[3];
    const float* W2 = (const float*)d_in[4];
    const float* b2 = (const float*)d_in[5];
    float* out = (float*)d_out;

    cudaFuncSetAttribute(moe_mma<false>, cudaFuncAttributeMaxDynamicSharedMemorySize,
                         SMEM_G1);
    cudaFuncSetAttribute(moe_mma<true>, cudaFuncAttributeMaxDynamicSharedMemorySize,
                         SMEM_G2);

    const int n4 = out_size / 4;
    zero_kernel<<<(n4 + 255) / 256, 256>>>((float4*)out, n4);
    router_kernel<<<T_TOK / 128, 256>>>(x, Wr);
    topk_kernel<<<E_EXP, 256>>>();
    gather_kernel<<<E_EXP * CAP, 256>>>(x);
    conv_kernel<<<dim3(40, 32, E_EXP * S_SHARD), 256>>>(W1, W2);
    moe_mma<false><<<dim3(4, 4, E_EXP * S_SHARD), 256, SMEM_G1>>>(b1, nullptr);
    moe_mma<true><<<dim3(1, 4, E_EXP * S_SHARD), 256, SMEM_G2>>>(b2, out);
}

// round 10
// speedup vs baseline: 1.3683x; 1.3683x over previous
#include <cuda_runtime.h>
#include <cuda_bf16.h>
#include <cuda_fp16.h>
#include <cstdint>
#include <math.h>

// ---------------------------------------------------------------------------
// EfficientMoEMLPBlock — expert-choice MoE MLP on sm_103 (portable PTX only).
//   E=48, S=4, D=1024, M=1024, K=D/S=256, T=16384, cap=512
// Round 10: plain fp16 single-rounded GEMMs (x, W1, h, W2 each rounded once;
//           error ~5e-4 < 1e-3). R7 geometry restored: CTA 128x128, warp
//           64x32, occupancy 2, 3-stage cp.async, stage = Ah|Bf (16KB).
// ---------------------------------------------------------------------------

#define T_TOK   16384
#define D_DIM   1024
#define E_EXP   48
#define S_SHARD 4
#define M_DIM   1024
#define K_DIM   256
#define CAP     512

typedef unsigned int uint32;
typedef unsigned long long uint64;

// ------------------------- scratch (device globals) ------------------------
__device__ float g_logits[(size_t)E_EXP * T_TOK];
__device__ int   g_idx[E_EXP * CAP];
__device__ float g_w[E_EXP * CAP];
__device__ __half g_xgh[(size_t)E_EXP * CAP * D_DIM];
__device__ __half g_w1h[(size_t)E_EXP * S_SHARD * M_DIM * D_DIM];  // [es][m][d]
__device__ __half g_w2h[(size_t)E_EXP * S_SHARD * K_DIM * M_DIM];  // [es][k][m]
__device__ __half g_hh[(size_t)E_EXP * S_SHARD * CAP * M_DIM];     // [es][c][m]

// ------------------------------- helpers -----------------------------------
__device__ __forceinline__ unsigned fkey(float f) {
    unsigned u = __float_as_uint(f);
    return (u & 0x80000000u) ? ~u : (u | 0x80000000u);
}
__device__ __forceinline__ float gelu_f(float v) {
    return 0.5f * v * (1.0f + erff(v * 0.70710678118654752440f));
}
__device__ __forceinline__ uint32 pack_hf(__half a, __half b) {
    return (uint32)__half_as_ushort(a) | ((uint32)__half_as_ushort(b) << 16);
}
__device__ __forceinline__ uint32 smem_u32(const void* p) {
    uint32 a;
    asm("{ .reg .u64 t; cvta.to.shared.u64 t, %1; cvt.u32.u64 %0, t; }" : "=r"(a) : "l"(p));
    return a;
}
// packed-swizzle smem layout: 2 logical rows (64B each) per 128B physical row;
// 16B chunks XOR-swizzled so 8 consecutive rows at fixed chunk are conflict-free.
__device__ __forceinline__ int phys(int r, int c) {
    return ((r >> 1) << 7) + (((((r & 1) << 2) | c) ^ ((r >> 1) & 7)) << 4);
}
__device__ __forceinline__ void cp_async16(uint32 saddr, const void* gaddr) {
    asm volatile("cp.async.cg.shared.global [%0], [%1], 16;"
                 :: "r"(saddr), "l"(gaddr) : "memory");
}
#define CP_COMMIT() asm volatile("cp.async.commit_group;" ::: "memory")
#define CP_WAIT(n)  asm volatile("cp.async.wait_group %0;" :: "n"(n) : "memory")

__device__ __forceinline__ void ldsm4(uint32* r, uint32 addr) {
    asm volatile("ldmatrix.sync.aligned.m8n8.x4.shared.b16 {%0,%1,%2,%3}, [%4];"
                 : "=r"(r[0]), "=r"(r[1]), "=r"(r[2]), "=r"(r[3]) : "r"(addr));
}
__device__ __forceinline__ void mma16816(float* c, const uint32* a, const uint32* b) {
    asm volatile(
        "mma.sync.aligned.m16n8k16.row.col.f32.f16.f16.f32 "
        "{%0,%1,%2,%3}, {%4,%5,%6,%7}, {%8,%9}, {%0,%1,%2,%3};"
        : "+f"(c[0]), "+f"(c[1]), "+f"(c[2]), "+f"(c[3])
        : "r"(a[0]), "r"(a[1]), "r"(a[2]), "r"(a[3]), "r"(b[0]), "r"(b[1]));
}
#define FENCE_ASYNC() asm volatile("fence.proxy.async.shared::cta;" ::: "memory")

// ------------------------------ zero out -----------------------------------
__global__ void zero_kernel(float4* __restrict__ p, int n4) {
    int i = blockIdx.x * blockDim.x + threadIdx.x;
    if (i < n4) p[i] = make_float4(0.f, 0.f, 0.f, 0.f);
}

// ------------------------- router logits [E][T] ----------------------------
__global__ __launch_bounds__(256) void router_kernel(const float* __restrict__ x,
                                                     const float* __restrict__ Wr) {
    __shared__ float xs[32][129];
    __shared__ float ws[32][49];
    const int tid = threadIdx.x;
    const int tb  = blockIdx.x * 128;
    const int t0  = (tid & 31) * 4;
    const int e0  = (tid >> 5) * 6;

    float acc[4][6];
#pragma unroll
    for (int i = 0; i < 4; i++)
#pragma unroll
        for (int j = 0; j < 6; j++) acc[i][j] = 0.f;

    for (int kb = 0; kb < D_DIM; kb += 32) {
        __syncthreads();
        for (int i = tid; i < 128 * 32; i += 256) {
            int r = i >> 5, c = i & 31;
            xs[c][r] = x[(size_t)(tb + r) * D_DIM + kb + c];
        }
        for (int i = tid; i < E_EXP * 32; i += 256) {
            int r = i >> 5, c = i & 31;
            ws[c][r] = Wr[(size_t)r * D_DIM + kb + c];
        }
        __syncthreads();
#pragma unroll 8
        for (int kk = 0; kk < 32; kk++) {
            float xv[4], wv[6];
#pragma unroll
            for (int i = 0; i < 4; i++) xv[i] = xs[kk][t0 + i];
#pragma unroll
            for (int j = 0; j < 6; j++) wv[j] = ws[kk][e0 + j];
#pragma unroll
            for (int i = 0; i < 4; i++)
#pragma unroll
                for (int j = 0; j < 6; j++) acc[i][j] += xv[i] * wv[j];
        }
    }
#pragma unroll
    for (int j = 0; j < 6; j++)
#pragma unroll
        for (int i = 0; i < 4; i++)
            g_logits[(size_t)(e0 + j) * T_TOK + tb + t0 + i] = acc[i][j];
}

// -------------------- per-expert top-512 + softmax --------------------------
__global__ __launch_bounds__(256) void topk_kernel() {
    const int e = blockIdx.x;
    const float* lg = g_logits + (size_t)e * T_TOK;
    const int tid = threadIdx.x;

    __shared__ unsigned hist[4096];
    __shared__ unsigned csum[256];
    __shared__ int      eq_idx[256];
    __shared__ float    svals[CAP];
    __shared__ float    sred[256];
    __shared__ unsigned s_binA, s_cntA, s_binB, s_cntB, s_key;
    __shared__ unsigned s_pos, s_eqcnt;

    for (int i = tid; i < 4096; i += 256) hist[i] = 0;
    __syncthreads();
    for (int t = tid; t < T_TOK; t += 256) {
        unsigned k = fkey(lg[t]);
        atomicAdd(&hist[k >> 20], 1u);
    }
    __syncthreads();
    {
        unsigned s = 0;
#pragma unroll
        for (int j = 0; j < 16; j++) s += hist[tid * 16 + j];
        csum[tid] = s;
    }
    __syncthreads();
    if (tid == 0) {
        unsigned need = CAP, cum = 0;
        int chunk = 0;
        for (int c = 255; c >= 0; c--) {
            if (cum + csum[c] >= need) { chunk = c; break; }
            cum += csum[c];
        }
        int bsel = chunk * 16;
        for (int b = chunk * 16 + 15; b >= chunk * 16; b--) {
            if (cum + hist[b] >= need) { bsel = b; break; }
            cum += hist[b];
        }
        s_binA = (unsigned)bsel;
        s_cntA = cum;
    }
    __syncthreads();
    const unsigned binA = s_binA, cntA = s_cntA;

    for (int i = tid; i < 4096; i += 256) hist[i] = 0;
    __syncthreads();
    for (int t = tid; t < T_TOK; t += 256) {
        unsigned k = fkey(lg[t]);
        if ((k >> 20) == binA) atomicAdd(&hist[(k >> 8) & 0xFFFu], 1u);
    }
    __syncthreads();
    {
        unsigned s = 0;
#pragma unroll
        for (int j = 0; j < 16; j++) s += hist[tid * 16 + j];
        csum[tid] = s;
    }
    __syncthreads();
    if (tid == 0) {
        unsigned need = CAP - cntA, cum = 0;
        int chunk = 0;
        for (int c = 255; c >= 0; c--) {
            if (cum + csum[c] >= need) { chunk = c; break; }
            cum += csum[c];
        }
        int bsel = chunk * 16;
        for (int b = chunk * 16 + 15; b >= chunk * 16; b--) {
            if (cum + hist[b] >= need) { bsel = b; break; }
            cum += hist[b];
        }
        s_binB = (unsigned)bsel;
        s_cntB = cum;
    }
    __syncthreads();
    const unsigned binB = s_binB, cntB = s_cntB;
    const unsigned prefix = (binA << 12) | binB;

    for (int i = tid; i < 256; i += 256) hist[i] = 0;
    __syncthreads();
    for (int t = tid; t < T_TOK; t += 256) {
        unsigned k = fkey(lg[t]);
        if ((k >> 8) == prefix) atomicAdd(&hist[k & 0xFFu], 1u);
    }
    __syncthreads();
    if (tid == 0) {
        unsigned need = CAP - cntA - cntB, cum = 0;
        int bsel = 0;
        for (int b = 255; b >= 0; b--) {
            if (cum + hist[b] >= need) { bsel = b; break; }
            cum += hist[b];
        }
        s_key = (prefix << 8) | (unsigned)bsel;
        s_pos = 0;
        s_eqcnt = 0;
    }
    __syncthreads();
    const unsigned ukey = s_key;

    for (int t = tid; t < T_TOK; t += 256) {
        float v = lg[t];
        unsigned k = fkey(v);
        if (k > ukey) {
            unsigned p = atomicAdd(&s_pos, 1u);
            g_idx[e * CAP + p] = t;
            svals[p] = v;
        } else if (k == ukey) {
            unsigned q = atomicAdd(&s_eqcnt, 1u);
            if (q < 256) eq_idx[q] = t;
        }
    }
    __syncthreads();
    if (tid == 0) {
        int ngt  = (int)s_pos;
        int need = CAP - ngt;
        int m    = (int)(s_eqcnt < 256u ? s_eqcnt : 256u);
        for (int i = 0; i < need; i++) {
            int best = 0x7fffffff, bj = -1;
            for (int j = 0; j < m; j++)
                if (eq_idx[j] < best) { best = eq_idx[j]; bj = j; }
            eq_idx[bj] = 0x7fffffff;
            g_idx[e * CAP + ngt + i] = best;
            svals[ngt + i] = lg[best];
        }
    }
    __syncthreads();

    float mx = -3.4e38f;
    for (int i = tid; i < CAP; i += 256) mx = fmaxf(mx, svals[i]);
    sred[tid] = mx;
    __syncthreads();
    for (int o = 128; o > 0; o >>= 1) {
        if (tid < o) sred[tid] = fmaxf(sred[tid], sred[tid + o]);
        __syncthreads();
    }
    const float vmax = sred[0];
    __syncthreads();
    float sum = 0.f;
    for (int i = tid; i < CAP; i += 256) sum += expf(svals[i] - vmax);
    sred[tid] = sum;
    __syncthreads();
    for (int o = 128; o > 0; o >>= 1) {
        if (tid < o) sred[tid] += sred[tid + o];
        __syncthreads();
    }
    const float tot = sred[0];
    __syncthreads();
    for (int i = tid; i < CAP; i += 256)
        g_w[e * CAP + i] = expf(svals[i] - vmax) / tot;
}

// --------------------------- gather + fp16 round ----------------------------
__global__ __launch_bounds__(256) void gather_kernel(const float* __restrict__ x) {
    const int ec = blockIdx.x;
    const int t  = g_idx[ec];
    float4 v = ((const float4*)(x + (size_t)t * D_DIM))[threadIdx.x];
    uint2 hh = make_uint2(pack_hf(__float2half_rn(v.x), __float2half_rn(v.y)),
                          pack_hf(__float2half_rn(v.z), __float2half_rn(v.w)));
    ((uint2*)(g_xgh + (size_t)ec * D_DIM))[threadIdx.x] = hh;
}

// ---- fused weight transpose + fp16 round  [es][R][C] -> [es][C][R] ---------
__global__ __launch_bounds__(256) void conv_kernel(const float* __restrict__ W1,
                                                   const float* __restrict__ W2) {
    __shared__ float t[32][33];
    const bool is1 = blockIdx.x < 32;
    const int bx = is1 ? blockIdx.x : blockIdx.x - 32;
    const int es = blockIdx.z;
    const int C  = is1 ? 1024 : 256;
    const float* in = is1 ? W1 : W2;
    __half* outp = is1 ? g_w1h : g_w2h;

    const int c0 = bx * 32, r0 = blockIdx.y * 32;
    const int tx = threadIdx.x & 31, ty = threadIdx.x >> 5;
    const float* ip = in + (size_t)es * 1024 * C;
#pragma unroll
    for (int j = 0; j < 4; j++) {
        int r = ty + j * 8;
        t[r][tx] = ip[(size_t)(r0 + r) * C + c0 + tx];
    }
    __syncthreads();
    const size_t ob = (size_t)es * 1024 * C;
#pragma unroll
    for (int j = 0; j < 4; j++) {
        int rr = ty + j * 8;
        outp[ob + (size_t)(c0 + rr) * 1024 + r0 + tx] = __float2half_rn(t[tx][rr]);
    }
}

// -------------------- mma.sync fp16 GEMM, CTA 128x128 -----------------------
// 8 warps (2 x 4), warp tile 64x32, K=1024 in 32 chunks of 32.
// stage = Ah(8KB) | Bf(8KB) = 16KB; 3 stages = 48KB.
// Epilogue reuses smem as C tile 128x132 fp32 = 67.6KB; smem = 67.6KB, occ 2.
#define NCK 32
#define STG_BYTES 16384
#define SMEM_GEMM (128 * 132 * 4)

template <bool IS_G2>
__global__ __launch_bounds__(256, 2) void moe_mma(const float* __restrict__ bias_g,
                                                  float* __restrict__ out) {
    extern __shared__ char smem[];
    __shared__ float bias_s[128];
    const int es   = blockIdx.z, e = es >> 2, s = es & 3;
    const int row0 = blockIdx.y * 128;
    const int col0 = blockIdx.x * 128;
    const int tid  = threadIdx.x;
    const int lane = tid & 31, wid = tid >> 5;
    const int warpM = wid >> 2, warpN = wid & 3;
    const uint32 sb = smem_u32(smem);

    const __half* Aph = (IS_G2 ? g_hh + (size_t)es * CAP * M_DIM
                               : g_xgh + (size_t)e * CAP * D_DIM) + (size_t)row0 * 1024;
    const __half* Bpf = (IS_G2 ? g_w2h + (size_t)es * K_DIM * M_DIM
                               : g_w1h + (size_t)es * M_DIM * D_DIM) + (size_t)col0 * 1024;

    // per-thread cp.async slots: 1024 16B-chunks per stage / 256 thr = 4
    uint32 soff[4];
    const __half* gp[4];
#pragma unroll
    for (int i = 0; i < 4; i++) {
        int idx = tid + i * 256;
        if (idx < 512) {
            int r = idx >> 2, c = idx & 3;
            soff[i] = (uint32)phys(r, c);
            gp[i] = Aph + r * 1024 + c * 8;
        } else {
            int w = idx - 512;
            int r = w >> 2, c = w & 3;
            soff[i] = (uint32)(8192 + phys(r, c));
            gp[i] = Bpf + r * 1024 + c * 8;
        }
    }

    float acc[4][4][4];
#pragma unroll
    for (int mi = 0; mi < 4; mi++)
#pragma unroll
        for (int ni = 0; ni < 4; ni++)
#pragma unroll
            for (int q = 0; q < 4; q++) acc[mi][ni][q] = 0.f;

    // prologue: stages 0,1
#pragma unroll
    for (int st = 0; st < 2; st++) {
        const int kb = st * 32;
#pragma unroll
        for (int i = 0; i < 4; i++)
            cp_async16(sb + st * STG_BYTES + soff[i], gp[i] + kb);
        CP_COMMIT();
    }

    for (int ck = 0; ck < NCK; ck++) {
        CP_WAIT(1);
        __syncthreads();
        if (ck + 2 < NCK) {
            const int st = (ck + 2) % 3;
            const int kb = (ck + 2) * 32;
#pragma unroll
            for (int i = 0; i < 4; i++)
                cp_async16(sb + st * STG_BYTES + soff[i], gp[i] + kb);
        }
        CP_COMMIT();

        const uint32 s0 = sb + (ck % 3) * STG_BYTES;
#pragma unroll
        for (int kh = 0; kh < 2; kh++) {
            uint32 Bf[2][4];
#pragma unroll
            for (int np = 0; np < 2; np++) {
                int nr = warpN * 32 + np * 16 + ((lane >> 4) << 3) + (lane & 7);
                int ch = kh * 2 + ((lane >> 3) & 1);
                ldsm4(Bf[np], s0 + 8192 + phys(nr, ch));
            }
#pragma unroll
            for (int mi = 0; mi < 4; mi++) {
                int ar = warpM * 64 + mi * 16 + (lane & 15);
                int ch = kh * 2 + (lane >> 4);
                uint32 Ah[4];
                ldsm4(Ah, s0 + phys(ar, ch));
#pragma unroll
                for (int ni = 0; ni < 4; ni++) {
                    const uint32* bf = &Bf[ni >> 1][(ni & 1) * 2];
                    mma16816(acc[mi][ni], Ah, bf);
                }
            }
        }
    }

    CP_WAIT(0);
    __syncthreads();

    // ------------------------------ epilogue -------------------------------
    const int NB = IS_G2 ? K_DIM : M_DIM;
    if (tid < 128) bias_s[tid] = bias_g[(size_t)es * NB + col0 + tid];
    __syncthreads();

    float* Cs = (float*)smem;   // [128][132]
    if (!IS_G2) {
#pragma unroll
        for (int mi = 0; mi < 4; mi++)
#pragma unroll
            for (int ni = 0; ni < 4; ni++) {
                int r0 = warpM * 64 + mi * 16 + (lane >> 2);
                int c0 = warpN * 32 + ni * 8 + (lane & 3) * 2;
                Cs[r0 * 132 + c0]       = acc[mi][ni][0];
                Cs[r0 * 132 + c0 + 1]   = acc[mi][ni][1];
                Cs[(r0 + 8) * 132 + c0]     = acc[mi][ni][2];
                Cs[(r0 + 8) * 132 + c0 + 1] = acc[mi][ni][3];
            }
        __syncthreads();
        uint32* dh = (uint32*)g_hh;
        const size_t rowbase = (size_t)es * CAP + row0;
#pragma unroll 4
        for (int it = 0; it < 32; it++) {
            int idx = tid + it * 256;
            int r = idx >> 6, cp = idx & 63;
            float v0 = gelu_f(Cs[r * 132 + cp * 2]     + bias_s[cp * 2]);
            float v1 = gelu_f(Cs[r * 132 + cp * 2 + 1] + bias_s[cp * 2 + 1]);
            dh[(rowbase + r) * 512 + (col0 >> 1) + cp] =
                pack_hf(__float2half_rn(v0), __float2half_rn(v1));
        }
    } else {
        // apply bias + routing weight while staging, then bulk reduce-add rows
        float wv[8];
#pragma unroll
        for (int mi = 0; mi < 4; mi++) {
            wv[mi * 2]     = g_w[e * CAP + row0 + warpM * 64 + mi * 16 + (lane >> 2)];
            wv[mi * 2 + 1] = g_w[e * CAP + row0 + warpM * 64 + mi * 16 + (lane >> 2) + 8];
        }
#pragma unroll
        for (int mi = 0; mi < 4; mi++)
#pragma unroll
            for (int ni = 0; ni < 4; ni++) {
                int r0 = warpM * 64 + mi * 16 + (lane >> 2);
                int c0 = warpN * 32 + ni * 8 + (lane & 3) * 2;
                Cs[r0 * 132 + c0]       = (acc[mi][ni][0] + bias_s[c0])     * wv[mi * 2];
                Cs[r0 * 132 + c0 + 1]   = (acc[mi][ni][1] + bias_s[c0 + 1]) * wv[mi * 2];
                Cs[(r0 + 8) * 132 + c0]     = (acc[mi][ni][2] + bias_s[c0])     * wv[mi * 2 + 1];
                Cs[(r0 + 8) * 132 + c0 + 1] = (acc[mi][ni][3] + bias_s[c0 + 1]) * wv[mi * 2 + 1];
            }
        __syncthreads();
        FENCE_ASYNC();
        if (tid < 128) {
            const int r = tid;
            const int tok = g_idx[e * CAP + row0 + r];
            float* gdst = out + (size_t)tok * D_DIM + s * K_DIM + col0;
            uint32 sa = sb + (uint32)r * 132 * 4;
            asm volatile(
                "cp.reduce.async.bulk.global.shared::cta.bulk_group.add.f32 [%0], [%1], %2;"
                :: "l"(gdst), "r"(sa), "r"(512u) : "memory");
            asm volatile("cp.async.bulk.commit_group;" ::: "memory");
            asm volatile("cp.async.bulk.wait_group 0;" ::: "memory");
        }
        __syncthreads();
    }
}

// ------------------------------ launch -------------------------------------
extern "C" void kernel_launch(void* const* d_in, const int* in_sizes, int n_in,
                              void* d_out, int out_size) {
    const float* x  = (const float*)d_in[0];
    const float* Wr = (const float*)d_in[1];
    const float* W1 = (const float*)d_in[2];
    const float* b1 = (const float*)d_in[3];
    const float* W2 = (const float*)d_in[4];
    const float* b2 = (const float*)d_in[5];
    float* out = (float*)d_out;

    cudaFuncSetAttribute(moe_mma<false>, cudaFuncAttributeMaxDynamicSharedMemorySize,
                         SMEM_GEMM);
    cudaFuncSetAttribute(moe_mma<true>, cudaFuncAttributeMaxDynamicSharedMemorySize,
                         SMEM_GEMM);

    const int n4 = out_size / 4;
    zero_kernel<<<(n4 + 255) / 256, 256>>>((float4*)out, n4);
    router_kernel<<<T_TOK / 128, 256>>>(x, Wr);
    topk_kernel<<<E_EXP, 256>>>();
    gather_kernel<<<E_EXP * CAP, 256>>>(x);
    conv_kernel<<<dim3(40, 32, E_EXP * S_SHARD), 256>>>(W1, W2);
    moe_mma<false><<<dim3(8, 4, E_EXP * S_SHARD), 256, SMEM_GEMM>>>(b1, nullptr);
    moe_mma<true><<<dim3(2, 4, E_EXP * S_SHARD), 256, SMEM_GEMM>>>(b2, out);
}

// round 11
// speedup vs baseline: 1.4923x; 1.0906x over previous
#include <cuda_runtime.h>
#include <cuda_bf16.h>
#include <cuda_fp16.h>
#include <cstdint>
#include <math.h>

// ---------------------------------------------------------------------------
// EfficientMoEMLPBlock — expert-choice MoE MLP on sm_103 (portable PTX only).
//   E=48, S=4, D=1024, M=1024, K=D/S=256, T=16384, cap=512
// Round 11: conv kernel eliminated — GEMMs load W fp32 via cp.async and
//           convert to fp16 in smem (double-buffered), B fragments via
//           ldmatrix.x4.trans. CTA 256x128, 512 thr, warp tile 64x32.
// ---------------------------------------------------------------------------

#define T_TOK   16384
#define D_DIM   1024
#define E_EXP   48
#define S_SHARD 4
#define M_DIM   1024
#define K_DIM   256
#define CAP     512

typedef unsigned int uint32;
typedef unsigned long long uint64;

// ------------------------- scratch (device globals) ------------------------
__device__ float g_logits[(size_t)E_EXP * T_TOK];
__device__ int   g_idx[E_EXP * CAP];
__device__ float g_w[E_EXP * CAP];
__device__ __half g_xgh[(size_t)E_EXP * CAP * D_DIM];
__device__ __half g_hh[(size_t)E_EXP * S_SHARD * CAP * M_DIM];   // [es][c][m]

// ------------------------------- helpers -----------------------------------
__device__ __forceinline__ unsigned fkey(float f) {
    unsigned u = __float_as_uint(f);
    return (u & 0x80000000u) ? ~u : (u | 0x80000000u);
}
__device__ __forceinline__ float gelu_f(float v) {
    return 0.5f * v * (1.0f + erff(v * 0.70710678118654752440f));
}
__device__ __forceinline__ uint32 pack_hf(__half a, __half b) {
    return (uint32)__half_as_ushort(a) | ((uint32)__half_as_ushort(b) << 16);
}
__device__ __forceinline__ uint32 packf2(float a, float b) {
    __half2 h = __floats2half2_rn(a, b);
    return *(uint32*)&h;
}
__device__ __forceinline__ uint32 smem_u32(const void* p) {
    uint32 a;
    asm("{ .reg .u64 t; cvta.to.shared.u64 t, %1; cvt.u32.u64 %0, t; }" : "=r"(a) : "l"(p));
    return a;
}
// A-side packed swizzle: 2 logical 64B rows per 128B physical row.
__device__ __forceinline__ int phys(int r, int c) {
    return ((r >> 1) << 7) + (((((r & 1) << 2) | c) ^ ((r >> 1) & 7)) << 4);
}
__device__ __forceinline__ void cp_async16(uint32 saddr, const void* gaddr) {
    asm volatile("cp.async.cg.shared.global [%0], [%1], 16;"
                 :: "r"(saddr), "l"(gaddr) : "memory");
}
#define CP_COMMIT() asm volatile("cp.async.commit_group;" ::: "memory")
#define CP_WAIT1()  asm volatile("cp.async.wait_group 1;" ::: "memory")
#define CP_WAIT0()  asm volatile("cp.async.wait_group 0;" ::: "memory")

__device__ __forceinline__ void ldsm4(uint32* r, uint32 addr) {
    asm volatile("ldmatrix.sync.aligned.m8n8.x4.shared.b16 {%0,%1,%2,%3}, [%4];"
                 : "=r"(r[0]), "=r"(r[1]), "=r"(r[2]), "=r"(r[3]) : "r"(addr));
}
__device__ __forceinline__ void ldsm4t(uint32* r, uint32 addr) {
    asm volatile("ldmatrix.sync.aligned.m8n8.x4.trans.shared.b16 {%0,%1,%2,%3}, [%4];"
                 : "=r"(r[0]), "=r"(r[1]), "=r"(r[2]), "=r"(r[3]) : "r"(addr));
}
__device__ __forceinline__ void mma16816(float* c, const uint32* a, const uint32* b) {
    asm volatile(
        "mma.sync.aligned.m16n8k16.row.col.f32.f16.f16.f32 "
        "{%0,%1,%2,%3}, {%4,%5,%6,%7}, {%8,%9}, {%0,%1,%2,%3};"
        : "+f"(c[0]), "+f"(c[1]), "+f"(c[2]), "+f"(c[3])
        : "r"(a[0]), "r"(a[1]), "r"(a[2]), "r"(a[3]), "r"(b[0]), "r"(b[1]));
}
#define FENCE_ASYNC() asm volatile("fence.proxy.async.shared::cta;" ::: "memory")

// ------------------------------ zero out -----------------------------------
__global__ void zero_kernel(float4* __restrict__ p, int n4) {
    int i = blockIdx.x * blockDim.x + threadIdx.x;
    if (i < n4) p[i] = make_float4(0.f, 0.f, 0.f, 0.f);
}

// ------------------------- router logits [E][T] ----------------------------
__global__ __launch_bounds__(256) void router_kernel(const float* __restrict__ x,
                                                     const float* __restrict__ Wr) {
    __shared__ float xs[32][129];
    __shared__ float ws[32][49];
    const int tid = threadIdx.x;
    const int tb  = blockIdx.x * 128;
    const int t0  = (tid & 31) * 4;
    const int e0  = (tid >> 5) * 6;

    float acc[4][6];
#pragma unroll
    for (int i = 0; i < 4; i++)
#pragma unroll
        for (int j = 0; j < 6; j++) acc[i][j] = 0.f;

    for (int kb = 0; kb < D_DIM; kb += 32) {
        __syncthreads();
        for (int i = tid; i < 128 * 32; i += 256) {
            int r = i >> 5, c = i & 31;
            xs[c][r] = x[(size_t)(tb + r) * D_DIM + kb + c];
        }
        for (int i = tid; i < E_EXP * 32; i += 256) {
            int r = i >> 5, c = i & 31;
            ws[c][r] = Wr[(size_t)r * D_DIM + kb + c];
        }
        __syncthreads();
#pragma unroll 8
        for (int kk = 0; kk < 32; kk++) {
            float xv[4], wv[6];
#pragma unroll
            for (int i = 0; i < 4; i++) xv[i] = xs[kk][t0 + i];
#pragma unroll
            for (int j = 0; j < 6; j++) wv[j] = ws[kk][e0 + j];
#pragma unroll
            for (int i = 0; i < 4; i++)
#pragma unroll
                for (int j = 0; j < 6; j++) acc[i][j] += xv[i] * wv[j];
        }
    }
#pragma unroll
    for (int j = 0; j < 6; j++)
#pragma unroll
        for (int i = 0; i < 4; i++)
            g_logits[(size_t)(e0 + j) * T_TOK + tb + t0 + i] = acc[i][j];
}

// -------------------- per-expert top-512 + softmax --------------------------
__global__ __launch_bounds__(256) void topk_kernel() {
    const int e = blockIdx.x;
    const float* lg = g_logits + (size_t)e * T_TOK;
    const int tid = threadIdx.x;

    __shared__ unsigned hist[4096];
    __shared__ unsigned csum[256];
    __shared__ int      eq_idx[256];
    __shared__ float    svals[CAP];
    __shared__ float    sred[256];
    __shared__ unsigned s_binA, s_cntA, s_binB, s_cntB, s_key;
    __shared__ unsigned s_pos, s_eqcnt;

    for (int i = tid; i < 4096; i += 256) hist[i] = 0;
    __syncthreads();
    for (int t = tid; t < T_TOK; t += 256) {
        unsigned k = fkey(lg[t]);
        atomicAdd(&hist[k >> 20], 1u);
    }
    __syncthreads();
    {
        unsigned s = 0;
#pragma unroll
        for (int j = 0; j < 16; j++) s += hist[tid * 16 + j];
        csum[tid] = s;
    }
    __syncthreads();
    if (tid == 0) {
        unsigned need = CAP, cum = 0;
        int chunk = 0;
        for (int c = 255; c >= 0; c--) {
            if (cum + csum[c] >= need) { chunk = c; break; }
            cum += csum[c];
        }
        int bsel = chunk * 16;
        for (int b = chunk * 16 + 15; b >= chunk * 16; b--) {
            if (cum + hist[b] >= need) { bsel = b; break; }
            cum += hist[b];
        }
        s_binA = (unsigned)bsel;
        s_cntA = cum;
    }
    __syncthreads();
    const unsigned binA = s_binA, cntA = s_cntA;

    for (int i = tid; i < 4096; i += 256) hist[i] = 0;
    __syncthreads();
    for (int t = tid; t < T_TOK; t += 256) {
        unsigned k = fkey(lg[t]);
        if ((k >> 20) == binA) atomicAdd(&hist[(k >> 8) & 0xFFFu], 1u);
    }
    __syncthreads();
    {
        unsigned s = 0;
#pragma unroll
        for (int j = 0; j < 16; j++) s += hist[tid * 16 + j];
        csum[tid] = s;
    }
    __syncthreads();
    if (tid == 0) {
        unsigned need = CAP - cntA, cum = 0;
        int chunk = 0;
        for (int c = 255; c >= 0; c--) {
            if (cum + csum[c] >= need) { chunk = c; break; }
            cum += csum[c];
        }
        int bsel = chunk * 16;
        for (int b = chunk * 16 + 15; b >= chunk * 16; b--) {
            if (cum + hist[b] >= need) { bsel = b; break; }
            cum += hist[b];
        }
        s_binB = (unsigned)bsel;
        s_cntB = cum;
    }
    __syncthreads();
    const unsigned binB = s_binB, cntB = s_cntB;
    const unsigned prefix = (binA << 12) | binB;

    for (int i = tid; i < 256; i += 256) hist[i] = 0;
    __syncthreads();
    for (int t = tid; t < T_TOK; t += 256) {
        unsigned k = fkey(lg[t]);
        if ((k >> 8) == prefix) atomicAdd(&hist[k & 0xFFu], 1u);
    }
    __syncthreads();
    if (tid == 0) {
        unsigned need = CAP - cntA - cntB, cum = 0;
        int bsel = 0;
        for (int b = 255; b >= 0; b--) {
            if (cum + hist[b] >= need) { bsel = b; break; }
            cum += hist[b];
        }
        s_key = (prefix << 8) | (unsigned)bsel;
        s_pos = 0;
        s_eqcnt = 0;
    }
    __syncthreads();
    const unsigned ukey = s_key;

    for (int t = tid; t < T_TOK; t += 256) {
        float v = lg[t];
        unsigned k = fkey(v);
        if (k > ukey) {
            unsigned p = atomicAdd(&s_pos, 1u);
            g_idx[e * CAP + p] = t;
            svals[p] = v;
        } else if (k == ukey) {
            unsigned q = atomicAdd(&s_eqcnt, 1u);
            if (q < 256) eq_idx[q] = t;
        }
    }
    __syncthreads();
    if (tid == 0) {
        int ngt  = (int)s_pos;
        int need = CAP - ngt;
        int m    = (int)(s_eqcnt < 256u ? s_eqcnt : 256u);
        for (int i = 0; i < need; i++) {
            int best = 0x7fffffff, bj = -1;
            for (int j = 0; j < m; j++)
                if (eq_idx[j] < best) { best = eq_idx[j]; bj = j; }
            eq_idx[bj] = 0x7fffffff;
            g_idx[e * CAP + ngt + i] = best;
            svals[ngt + i] = lg[best];
        }
    }
    __syncthreads();

    float mx = -3.4e38f;
    for (int i = tid; i < CAP; i += 256) mx = fmaxf(mx, svals[i]);
    sred[tid] = mx;
    __syncthreads();
    for (int o = 128; o > 0; o >>= 1) {
        if (tid < o) sred[tid] = fmaxf(sred[tid], sred[tid + o]);
        __syncthreads();
    }
    const float vmax = sred[0];
    __syncthreads();
    float sum = 0.f;
    for (int i = tid; i < CAP; i += 256) sum += expf(svals[i] - vmax);
    sred[tid] = sum;
    __syncthreads();
    for (int o = 128; o > 0; o >>= 1) {
        if (tid < o) sred[tid] += sred[tid + o];
        __syncthreads();
    }
    const float tot = sred[0];
    __syncthreads();
    for (int i = tid; i < CAP; i += 256)
        g_w[e * CAP + i] = expf(svals[i] - vmax) / tot;
}

// --------------------------- gather + fp16 round ----------------------------
__global__ __launch_bounds__(256) void gather_kernel(const float* __restrict__ x) {
    const int ec = blockIdx.x;
    const int t  = g_idx[ec];
    float4 v = ((const float4*)(x + (size_t)t * D_DIM))[threadIdx.x];
    uint2 hh = make_uint2(packf2(v.x, v.y), packf2(v.z, v.w));
    ((uint2*)(g_xgh + (size_t)ec * D_DIM))[threadIdx.x] = hh;
}

// ---------------- mma.sync fp16 GEMM with in-kernel W convert ---------------
// CTA 256(M) x 128(N), 512 threads, 16 warps (4x4), warp tile 64x32.
// K=1024 in 32 chunks of 32.
// smem map (bytes):
//   A fp16 stages  : 4 x 16384 at 0       (256 rows x 64B, phys swizzle)
//   B fp32 stages  : 3 x 16384 at 65536   (32 k-rows x 512B, linear)
//   B fp16 buffers : 2 x  8192 at 114688  ([k][n] n-contig, chunk^k swizzle)
//   epilogue C tile: 256 x 132 fp32 = 135168 (reuses everything)
#define NCK 32
#define A_ST   16384
#define B32_ST 16384
#define B32_BASE 65536
#define BF_BASE 114688
#define SMEM_GEMM (256 * 132 * 4)

template <bool IS_G2>
__global__ __launch_bounds__(512, 1) void moe_mma(const float* __restrict__ Bw,
                                                  const float* __restrict__ bias_g,
                                                  float* __restrict__ out) {
    extern __shared__ char smem[];
    __shared__ float bias_s[128];
    const int es   = blockIdx.z, e = es >> 2, s = es & 3;
    const int row0 = blockIdx.y * 256;
    const int col0 = blockIdx.x * 128;
    const int tid  = threadIdx.x;
    const int lane = tid & 31, wid = tid >> 5;
    const int warpM = wid >> 2, warpN = wid & 3;   // 4 x 4 warps
    const uint32 sb = smem_u32(smem);
    const int BSTR = IS_G2 ? K_DIM : M_DIM;

    const __half* Aph = (IS_G2 ? g_hh + (size_t)es * CAP * M_DIM
                               : g_xgh + (size_t)e * CAP * D_DIM) + (size_t)row0 * 1024;
    const float* Bp32 = Bw + (size_t)es * 1024 * BSTR + col0;

    // cp.async slots: A 1024 chunks + B32 1024 chunks over 512 threads
    uint32 soffA[2], soffB[2];
    const __half* gpA[2];
    const float*  gpB[2];
#pragma unroll
    for (int i = 0; i < 2; i++) {
        int idx = tid + i * 512;
        int r = idx >> 2, c = idx & 3;
        soffA[i] = (uint32)phys(r, c);
        gpA[i] = Aph + r * 1024 + c * 8;
        int kr = idx >> 5, cc = idx & 31;
        soffB[i] = (uint32)(idx * 16);
        gpB[i] = Bp32 + (size_t)kr * BSTR + cc * 4;
    }

    float acc[4][4][4];
#pragma unroll
    for (int mi = 0; mi < 4; mi++)
#pragma unroll
        for (int ni = 0; ni < 4; ni++)
#pragma unroll
            for (int q = 0; q < 4; q++) acc[mi][ni][q] = 0.f;

    // issue one chunk's loads (A stage c&3, B32 stage c%3)
    auto issue = [&](int c) {
        const uint32 ab = sb + (c & 3) * A_ST;
        const uint32 bb = sb + B32_BASE + (c % 3) * B32_ST;
        const int kb = c * 32;
#pragma unroll
        for (int i = 0; i < 2; i++) {
            cp_async16(ab + soffA[i], gpA[i] + kb);
            cp_async16(bb + soffB[i], gpB[i] + (size_t)kb * BSTR);
        }
        CP_COMMIT();
    };
    // convert chunk c's B fp32 -> fp16 buffer (c&1)
    auto convert = [&](int c) {
        const char* src = smem + B32_BASE + (c % 3) * B32_ST;
        char* dst = smem + BF_BASE + (c & 1) * 8192;
#pragma unroll
        for (int j = 0; j < 2; j++) {
            int q = tid + j * 512;
            int kr = q >> 5, c32 = q & 31;
            float4 v = *(const float4*)(src + q * 16);
            uint32 off = kr * 256 + ((((c32 >> 1) ^ (kr & 7)) << 4) | ((c32 & 1) << 3));
            *(uint2*)(dst + off) = make_uint2(packf2(v.x, v.y), packf2(v.z, v.w));
        }
    };

    issue(0);
    issue(1);
    CP_WAIT1();
    __syncthreads();
    convert(0);
    issue(2);

    for (int ck = 0; ck < NCK; ck++) {
        if (ck < 30) { CP_WAIT1(); } else { CP_WAIT0(); }
        __syncthreads();               // orders: prev MMA, convert visib, stages
        if (ck + 1 < NCK) convert(ck + 1);
        if (ck + 3 < NCK) issue(ck + 3);

        const uint32 s0a = sb + (ck & 3) * A_ST;
        const uint32 bufb = sb + BF_BASE + (ck & 1) * 8192;
#pragma unroll
        for (int kh = 0; kh < 2; kh++) {
            uint32 Bf[2][4];
#pragma unroll
            for (int np = 0; np < 2; np++) {
                int k = kh * 16 + (lane & 15);
                int chunk = warpN * 4 + np * 2 + (lane >> 4);
                ldsm4t(Bf[np], bufb + k * 256 + ((chunk ^ (k & 7)) << 4));
            }
#pragma unroll
            for (int mi = 0; mi < 4; mi++) {
                int ar = warpM * 64 + mi * 16 + (lane & 15);
                int ch = kh * 2 + (lane >> 4);
                uint32 Ah[4];
                ldsm4(Ah, s0a + phys(ar, ch));
#pragma unroll
                for (int ni = 0; ni < 4; ni++) {
                    const uint32* bf = &Bf[ni >> 1][(ni & 1) * 2];
                    mma16816(acc[mi][ni], Ah, bf);
                }
            }
        }
    }

    __syncthreads();

    // ------------------------------ epilogue -------------------------------
    const int NB = IS_G2 ? K_DIM : M_DIM;
    if (tid < 128) bias_s[tid] = bias_g[(size_t)es * NB + col0 + tid];
    __syncthreads();

    float* Cs = (float*)smem;   // [256][132]
    if (!IS_G2) {
#pragma unroll
        for (int mi = 0; mi < 4; mi++)
#pragma unroll
            for (int ni = 0; ni < 4; ni++) {
                int r0 = warpM * 64 + mi * 16 + (lane >> 2);
                int c0 = warpN * 32 + ni * 8 + (lane & 3) * 2;
                Cs[r0 * 132 + c0]       = acc[mi][ni][0];
                Cs[r0 * 132 + c0 + 1]   = acc[mi][ni][1];
                Cs[(r0 + 8) * 132 + c0]     = acc[mi][ni][2];
                Cs[(r0 + 8) * 132 + c0 + 1] = acc[mi][ni][3];
            }
        __syncthreads();
        uint32* dh = (uint32*)g_hh;
        const size_t rowbase = (size_t)es * CAP + row0;
#pragma unroll 4
        for (int it = 0; it < 32; it++) {
            int idx = tid + it * 512;
            int r = idx >> 6, cp = idx & 63;
            float v0 = gelu_f(Cs[r * 132 + cp * 2]     + bias_s[cp * 2]);
            float v1 = gelu_f(Cs[r * 132 + cp * 2 + 1] + bias_s[cp * 2 + 1]);
            dh[(rowbase + r) * 512 + (col0 >> 1) + cp] = packf2(v0, v1);
        }
    } else {
        float wv[8];
#pragma unroll
        for (int mi = 0; mi < 4; mi++) {
            wv[mi * 2]     = g_w[e * CAP + row0 + warpM * 64 + mi * 16 + (lane >> 2)];
            wv[mi * 2 + 1] = g_w[e * CAP + row0 + warpM * 64 + mi * 16 + (lane >> 2) + 8];
        }
#pragma unroll
        for (int mi = 0; mi < 4; mi++)
#pragma unroll
            for (int ni = 0; ni < 4; ni++) {
                int r0 = warpM * 64 + mi * 16 + (lane >> 2);
                int c0 = warpN * 32 + ni * 8 + (lane & 3) * 2;
                Cs[r0 * 132 + c0]       = (acc[mi][ni][0] + bias_s[c0])     * wv[mi * 2];
                Cs[r0 * 132 + c0 + 1]   = (acc[mi][ni][1] + bias_s[c0 + 1]) * wv[mi * 2];
                Cs[(r0 + 8) * 132 + c0]     = (acc[mi][ni][2] + bias_s[c0])     * wv[mi * 2 + 1];
                Cs[(r0 + 8) * 132 + c0 + 1] = (acc[mi][ni][3] + bias_s[c0 + 1]) * wv[mi * 2 + 1];
            }
        __syncthreads();
        FENCE_ASYNC();
        if (tid < 256) {
            const int r = tid;
            const int tok = g_idx[e * CAP + row0 + r];
            float* gdst = out + (size_t)tok * D_DIM + s * K_DIM + col0;
            uint32 sa = sb + (uint32)r * 132 * 4;
            asm volatile(
                "cp.reduce.async.bulk.global.shared::cta.bulk_group.add.f32 [%0], [%1], %2;"
                :: "l"(gdst), "r"(sa), "r"(512u) : "memory");
            asm volatile("cp.async.bulk.commit_group;" ::: "memory");
            asm volatile("cp.async.bulk.wait_group 0;" ::: "memory");
        }
        __syncthreads();
    }
}

// ------------------------------ launch -------------------------------------
extern "C" void kernel_launch(void* const* d_in, const int* in_sizes, int n_in,
                              void* d_out, int out_size) {
    const float* x  = (const float*)d_in[0];
    const float* Wr = (const float*)d_in[1];
    const float* W1 = (const float*)d_in[2];
    const float* b1 = (const float*)d_in[3];
    const float* W2 = (const float*)d_in[4];
    const float* b2 = (const float*)d_in[5];
    float* out = (float*)d_out;

    cudaFuncSetAttribute(moe_mma<false>, cudaFuncAttributeMaxDynamicSharedMemorySize,
                         SMEM_GEMM);
    cudaFuncSetAttribute(moe_mma<true>, cudaFuncAttributeMaxDynamicSharedMemorySize,
                         SMEM_GEMM);

    const int n4 = out_size / 4;
    zero_kernel<<<(n4 + 255) / 256, 256>>>((float4*)out, n4);
    router_kernel<<<T_TOK / 128, 256>>>(x, Wr);
    topk_kernel<<<E_EXP, 256>>>();
    gather_kernel<<<E_EXP * CAP, 256>>>(x);
    moe_mma<false><<<dim3(8, 2, E_EXP * S_SHARD), 512, SMEM_GEMM>>>(W1, b1, nullptr);
    moe_mma<true><<<dim3(2, 2, E_EXP * S_SHARD), 512, SMEM_GEMM>>>(W2, b2, out);
}

// round 12
// speedup vs baseline: 1.5922x; 1.0670x over previous
#include <cuda_runtime.h>
#include <cuda_bf16.h>
#include <cuda_fp16.h>
#include <cstdint>
#include <math.h>

// ---------------------------------------------------------------------------
// EfficientMoEMLPBlock — expert-choice MoE MLP on sm_103 (portable PTX only).
//   E=48, S=4, D=1024, M=1024, K=D/S=256, T=16384, cap=512
// Round 12: in-kernel W fp32->fp16 convert (R11) at occupancy 2 (R10 geom).
//           CTA 128x128, 256 thr, 8 warps (2x4), warp 64x32.
//           smem: A fp16 4-stage + B fp32 3-stage + B fp16 2-buf = 96KB.
// ---------------------------------------------------------------------------

#define T_TOK   16384
#define D_DIM   1024
#define E_EXP   48
#define S_SHARD 4
#define M_DIM   1024
#define K_DIM   256
#define CAP     512

typedef unsigned int uint32;
typedef unsigned long long uint64;

// ------------------------- scratch (device globals) ------------------------
__device__ float g_logits[(size_t)E_EXP * T_TOK];
__device__ int   g_idx[E_EXP * CAP];
__device__ float g_w[E_EXP * CAP];
__device__ __half g_xgh[(size_t)E_EXP * CAP * D_DIM];
__device__ __half g_hh[(size_t)E_EXP * S_SHARD * CAP * M_DIM];   // [es][c][m]

// ------------------------------- helpers -----------------------------------
__device__ __forceinline__ unsigned fkey(float f) {
    unsigned u = __float_as_uint(f);
    return (u & 0x80000000u) ? ~u : (u | 0x80000000u);
}
__device__ __forceinline__ float gelu_f(float v) {
    return 0.5f * v * (1.0f + erff(v * 0.70710678118654752440f));
}
__device__ __forceinline__ uint32 packf2(float a, float b) {
    __half2 h = __floats2half2_rn(a, b);
    return *(uint32*)&h;
}
__device__ __forceinline__ uint32 smem_u32(const void* p) {
    uint32 a;
    asm("{ .reg .u64 t; cvta.to.shared.u64 t, %1; cvt.u32.u64 %0, t; }" : "=r"(a) : "l"(p));
    return a;
}
// A-side packed swizzle: 2 logical 64B rows per 128B physical row.
__device__ __forceinline__ int phys(int r, int c) {
    return ((r >> 1) << 7) + (((((r & 1) << 2) | c) ^ ((r >> 1) & 7)) << 4);
}
__device__ __forceinline__ void cp_async16(uint32 saddr, const void* gaddr) {
    asm volatile("cp.async.cg.shared.global [%0], [%1], 16;"
                 :: "r"(saddr), "l"(gaddr) : "memory");
}
#define CP_COMMIT() asm volatile("cp.async.commit_group;" ::: "memory")
#define CP_WAIT1()  asm volatile("cp.async.wait_group 1;" ::: "memory")
#define CP_WAIT0()  asm volatile("cp.async.wait_group 0;" ::: "memory")

__device__ __forceinline__ void ldsm4(uint32* r, uint32 addr) {
    asm volatile("ldmatrix.sync.aligned.m8n8.x4.shared.b16 {%0,%1,%2,%3}, [%4];"
                 : "=r"(r[0]), "=r"(r[1]), "=r"(r[2]), "=r"(r[3]) : "r"(addr));
}
__device__ __forceinline__ void ldsm4t(uint32* r, uint32 addr) {
    asm volatile("ldmatrix.sync.aligned.m8n8.x4.trans.shared.b16 {%0,%1,%2,%3}, [%4];"
                 : "=r"(r[0]), "=r"(r[1]), "=r"(r[2]), "=r"(r[3]) : "r"(addr));
}
__device__ __forceinline__ void mma16816(float* c, const uint32* a, const uint32* b) {
    asm volatile(
        "mma.sync.aligned.m16n8k16.row.col.f32.f16.f16.f32 "
        "{%0,%1,%2,%3}, {%4,%5,%6,%7}, {%8,%9}, {%0,%1,%2,%3};"
        : "+f"(c[0]), "+f"(c[1]), "+f"(c[2]), "+f"(c[3])
        : "r"(a[0]), "r"(a[1]), "r"(a[2]), "r"(a[3]), "r"(b[0]), "r"(b[1]));
}
#define FENCE_ASYNC() asm volatile("fence.proxy.async.shared::cta;" ::: "memory")

// ------------------------------ zero out -----------------------------------
__global__ void zero_kernel(float4* __restrict__ p, int n4) {
    int i = blockIdx.x * blockDim.x + threadIdx.x;
    if (i < n4) p[i] = make_float4(0.f, 0.f, 0.f, 0.f);
}

// ------------------------- router logits [E][T] ----------------------------
__global__ __launch_bounds__(256) void router_kernel(const float* __restrict__ x,
                                                     const float* __restrict__ Wr) {
    __shared__ float xs[32][129];
    __shared__ float ws[32][49];
    const int tid = threadIdx.x;
    const int tb  = blockIdx.x * 128;
    const int t0  = (tid & 31) * 4;
    const int e0  = (tid >> 5) * 6;

    float acc[4][6];
#pragma unroll
    for (int i = 0; i < 4; i++)
#pragma unroll
        for (int j = 0; j < 6; j++) acc[i][j] = 0.f;

    for (int kb = 0; kb < D_DIM; kb += 32) {
        __syncthreads();
        for (int i = tid; i < 128 * 32; i += 256) {
            int r = i >> 5, c = i & 31;
            xs[c][r] = x[(size_t)(tb + r) * D_DIM + kb + c];
        }
        for (int i = tid; i < E_EXP * 32; i += 256) {
            int r = i >> 5, c = i & 31;
            ws[c][r] = Wr[(size_t)r * D_DIM + kb + c];
        }
        __syncthreads();
#pragma unroll 8
        for (int kk = 0; kk < 32; kk++) {
            float xv[4], wv[6];
#pragma unroll
            for (int i = 0; i < 4; i++) xv[i] = xs[kk][t0 + i];
#pragma unroll
            for (int j = 0; j < 6; j++) wv[j] = ws[kk][e0 + j];
#pragma unroll
            for (int i = 0; i < 4; i++)
#pragma unroll
                for (int j = 0; j < 6; j++) acc[i][j] += xv[i] * wv[j];
        }
    }
#pragma unroll
    for (int j = 0; j < 6; j++)
#pragma unroll
        for (int i = 0; i < 4; i++)
            g_logits[(size_t)(e0 + j) * T_TOK + tb + t0 + i] = acc[i][j];
}

// -------------------- per-expert top-512 + softmax --------------------------
__global__ __launch_bounds__(256) void topk_kernel() {
    const int e = blockIdx.x;
    const float* lg = g_logits + (size_t)e * T_TOK;
    const int tid = threadIdx.x;

    __shared__ unsigned hist[4096];
    __shared__ unsigned csum[256];
    __shared__ int      eq_idx[256];
    __shared__ float    svals[CAP];
    __shared__ float    sred[256];
    __shared__ unsigned s_binA, s_cntA, s_binB, s_cntB, s_key;
    __shared__ unsigned s_pos, s_eqcnt;

    for (int i = tid; i < 4096; i += 256) hist[i] = 0;
    __syncthreads();
    for (int t = tid; t < T_TOK; t += 256) {
        unsigned k = fkey(lg[t]);
        atomicAdd(&hist[k >> 20], 1u);
    }
    __syncthreads();
    {
        unsigned s = 0;
#pragma unroll
        for (int j = 0; j < 16; j++) s += hist[tid * 16 + j];
        csum[tid] = s;
    }
    __syncthreads();
    if (tid == 0) {
        unsigned need = CAP, cum = 0;
        int chunk = 0;
        for (int c = 255; c >= 0; c--) {
            if (cum + csum[c] >= need) { chunk = c; break; }
            cum += csum[c];
        }
        int bsel = chunk * 16;
        for (int b = chunk * 16 + 15; b >= chunk * 16; b--) {
            if (cum + hist[b] >= need) { bsel = b; break; }
            cum += hist[b];
        }
        s_binA = (unsigned)bsel;
        s_cntA = cum;
    }
    __syncthreads();
    const unsigned binA = s_binA, cntA = s_cntA;

    for (int i = tid; i < 4096; i += 256) hist[i] = 0;
    __syncthreads();
    for (int t = tid; t < T_TOK; t += 256) {
        unsigned k = fkey(lg[t]);
        if ((k >> 20) == binA) atomicAdd(&hist[(k >> 8) & 0xFFFu], 1u);
    }
    __syncthreads();
    {
        unsigned s = 0;
#pragma unroll
        for (int j = 0; j < 16; j++) s += hist[tid * 16 + j];
        csum[tid] = s;
    }
    __syncthreads();
    if (tid == 0) {
        unsigned need = CAP - cntA, cum = 0;
        int chunk = 0;
        for (int c = 255; c >= 0; c--) {
            if (cum + csum[c] >= need) { chunk = c; break; }
            cum += csum[c];
        }
        int bsel = chunk * 16;
        for (int b = chunk * 16 + 15; b >= chunk * 16; b--) {
            if (cum + hist[b] >= need) { bsel = b; break; }
            cum += hist[b];
        }
        s_binB = (unsigned)bsel;
        s_cntB = cum;
    }
    __syncthreads();
    const unsigned binB = s_binB, cntB = s_cntB;
    const unsigned prefix = (binA << 12) | binB;

    for (int i = tid; i < 256; i += 256) hist[i] = 0;
    __syncthreads();
    for (int t = tid; t < T_TOK; t += 256) {
        unsigned k = fkey(lg[t]);
        if ((k >> 8) == prefix) atomicAdd(&hist[k & 0xFFu], 1u);
    }
    __syncthreads();
    if (tid == 0) {
        unsigned need = CAP - cntA - cntB, cum = 0;
        int bsel = 0;
        for (int b = 255; b >= 0; b--) {
            if (cum + hist[b] >= need) { bsel = b; break; }
            cum += hist[b];
        }
        s_key = (prefix << 8) | (unsigned)bsel;
        s_pos = 0;
        s_eqcnt = 0;
    }
    __syncthreads();
    const unsigned ukey = s_key;

    for (int t = tid; t < T_TOK; t += 256) {
        float v = lg[t];
        unsigned k = fkey(v);
        if (k > ukey) {
            unsigned p = atomicAdd(&s_pos, 1u);
            g_idx[e * CAP + p] = t;
            svals[p] = v;
        } else if (k == ukey) {
            unsigned q = atomicAdd(&s_eqcnt, 1u);
            if (q < 256) eq_idx[q] = t;
        }
    }
    __syncthreads();
    if (tid == 0) {
        int ngt  = (int)s_pos;
        int need = CAP - ngt;
        int m    = (int)(s_eqcnt < 256u ? s_eqcnt : 256u);
        for (int i = 0; i < need; i++) {
            int best = 0x7fffffff, bj = -1;
            for (int j = 0; j < m; j++)
                if (eq_idx[j] < best) { best = eq_idx[j]; bj = j; }
            eq_idx[bj] = 0x7fffffff;
            g_idx[e * CAP + ngt + i] = best;
            svals[ngt + i] = lg[best];
        }
    }
    __syncthreads();

    float mx = -3.4e38f;
    for (int i = tid; i < CAP; i += 256) mx = fmaxf(mx, svals[i]);
    sred[tid] = mx;
    __syncthreads();
    for (int o = 128; o > 0; o >>= 1) {
        if (tid < o) sred[tid] = fmaxf(sred[tid], sred[tid + o]);
        __syncthreads();
    }
    const float vmax = sred[0];
    __syncthreads();
    float sum = 0.f;
    for (int i = tid; i < CAP; i += 256) sum += expf(svals[i] - vmax);
    sred[tid] = sum;
    __syncthreads();
    for (int o = 128; o > 0; o >>= 1) {
        if (tid < o) sred[tid] += sred[tid + o];
        __syncthreads();
    }
    const float tot = sred[0];
    __syncthreads();
    for (int i = tid; i < CAP; i += 256)
        g_w[e * CAP + i] = expf(svals[i] - vmax) / tot;
}

// --------------------------- gather + fp16 round ----------------------------
__global__ __launch_bounds__(256) void gather_kernel(const float* __restrict__ x) {
    const int ec = blockIdx.x;
    const int t  = g_idx[ec];
    float4 v = ((const float4*)(x + (size_t)t * D_DIM))[threadIdx.x];
    uint2 hh = make_uint2(packf2(v.x, v.y), packf2(v.z, v.w));
    ((uint2*)(g_xgh + (size_t)ec * D_DIM))[threadIdx.x] = hh;
}

// ---------------- mma.sync fp16 GEMM with in-kernel W convert ---------------
// CTA 128(M) x 128(N), 256 threads, 8 warps (2x4), warp tile 64x32.
// K=1024 in 32 chunks of 32.
// smem map (bytes):
//   A fp16 stages  : 4 x 8192  at 0       (128 rows x 64B, phys swizzle)
//   B fp32 stages  : 3 x 16384 at 32768   (32 k-rows x 512B, linear)
//   B fp16 buffers : 2 x 8192  at 81920   ([k][n] n-contig, chunk^k swizzle)
//   epilogue C tile: 128 x 132 fp32 = 67584 (reuses region)
#define NCK 32
#define A_ST     8192
#define B32_ST   16384
#define B32_BASE 32768
#define BF_BASE  81920
#define SMEM_GEMM 98304

template <bool IS_G2>
__global__ __launch_bounds__(256, 2) void moe_mma(const float* __restrict__ Bw,
                                                  const float* __restrict__ bias_g,
                                                  float* __restrict__ out) {
    extern __shared__ char smem[];
    __shared__ float bias_s[128];
    const int es   = blockIdx.z, e = es >> 2, s = es & 3;
    const int row0 = blockIdx.y * 128;
    const int col0 = blockIdx.x * 128;
    const int tid  = threadIdx.x;
    const int lane = tid & 31, wid = tid >> 5;
    const int warpM = wid >> 2, warpN = wid & 3;   // 2 x 4 warps
    const uint32 sb = smem_u32(smem);
    const int BSTR = IS_G2 ? K_DIM : M_DIM;

    const __half* Aph = (IS_G2 ? g_hh + (size_t)es * CAP * M_DIM
                               : g_xgh + (size_t)e * CAP * D_DIM) + (size_t)row0 * 1024;
    const float* Bp32 = Bw + (size_t)es * 1024 * BSTR + col0;

    // cp.async slots: A 512 chunks (2/thr) + B32 1024 chunks (4/thr)
    uint32 soffA[2], soffB[4];
    const __half* gpA[2];
    const float*  gpB[4];
#pragma unroll
    for (int i = 0; i < 2; i++) {
        int idx = tid + i * 256;
        int r = idx >> 2, c = idx & 3;
        soffA[i] = (uint32)phys(r, c);
        gpA[i] = Aph + r * 1024 + c * 8;
    }
#pragma unroll
    for (int i = 0; i < 4; i++) {
        int idx = tid + i * 256;
        int kr = idx >> 5, cc = idx & 31;
        soffB[i] = (uint32)(idx * 16);
        gpB[i] = Bp32 + (size_t)kr * BSTR + cc * 4;
    }

    float acc[4][4][4];
#pragma unroll
    for (int mi = 0; mi < 4; mi++)
#pragma unroll
        for (int ni = 0; ni < 4; ni++)
#pragma unroll
            for (int q = 0; q < 4; q++) acc[mi][ni][q] = 0.f;

    // issue one chunk's loads (A stage c&3, B32 stage c%3)
    auto issue = [&](int c) {
        const uint32 ab = sb + (c & 3) * A_ST;
        const uint32 bb = sb + B32_BASE + (c % 3) * B32_ST;
        const int kb = c * 32;
#pragma unroll
        for (int i = 0; i < 2; i++)
            cp_async16(ab + soffA[i], gpA[i] + kb);
#pragma unroll
        for (int i = 0; i < 4; i++)
            cp_async16(bb + soffB[i], gpB[i] + (size_t)kb * BSTR);
        CP_COMMIT();
    };
    // convert chunk c's B fp32 -> fp16 buffer (c&1)
    auto convert = [&](int c) {
        const char* src = smem + B32_BASE + (c % 3) * B32_ST;
        char* dst = smem + BF_BASE + (c & 1) * 8192;
#pragma unroll
        for (int j = 0; j < 4; j++) {
            int q = tid + j * 256;
            int kr = q >> 5, c32 = q & 31;
            float4 v = *(const float4*)(src + q * 16);
            uint32 off = kr * 256 + ((((c32 >> 1) ^ (kr & 7)) << 4) | ((c32 & 1) << 3));
            *(uint2*)(dst + off) = make_uint2(packf2(v.x, v.y), packf2(v.z, v.w));
        }
    };

    issue(0);
    issue(1);
    CP_WAIT1();
    __syncthreads();
    convert(0);
    issue(2);

    for (int ck = 0; ck < NCK; ck++) {
        if (ck < 30) { CP_WAIT1(); } else { CP_WAIT0(); }
        __syncthreads();               // orders: prev MMA, convert visib, stages
        if (ck + 1 < NCK) convert(ck + 1);
        if (ck + 3 < NCK) issue(ck + 3);

        const uint32 s0a = sb + (ck & 3) * A_ST;
        const uint32 bufb = sb + BF_BASE + (ck & 1) * 8192;
#pragma unroll
        for (int kh = 0; kh < 2; kh++) {
            uint32 Bf[2][4];
#pragma unroll
            for (int np = 0; np < 2; np++) {
                int k = kh * 16 + (lane & 15);
                int chunk = warpN * 4 + np * 2 + (lane >> 4);
                ldsm4t(Bf[np], bufb + k * 256 + ((chunk ^ (k & 7)) << 4));
            }
#pragma unroll
            for (int mi = 0; mi < 4; mi++) {
                int ar = warpM * 64 + mi * 16 + (lane & 15);
                int ch = kh * 2 + (lane >> 4);
                uint32 Ah[4];
                ldsm4(Ah, s0a + phys(ar, ch));
#pragma unroll
                for (int ni = 0; ni < 4; ni++) {
                    const uint32* bf = &Bf[ni >> 1][(ni & 1) * 2];
                    mma16816(acc[mi][ni], Ah, bf);
                }
            }
        }
    }

    __syncthreads();

    // ------------------------------ epilogue -------------------------------
    const int NB = IS_G2 ? K_DIM : M_DIM;
    if (tid < 128) bias_s[tid] = bias_g[(size_t)es * NB + col0 + tid];
    __syncthreads();

    float* Cs = (float*)smem;   // [128][132]
    if (!IS_G2) {
#pragma unroll
        for (int mi = 0; mi < 4; mi++)
#pragma unroll
            for (int ni = 0; ni < 4; ni++) {
                int r0 = warpM * 64 + mi * 16 + (lane >> 2);
                int c0 = warpN * 32 + ni * 8 + (lane & 3) * 2;
                Cs[r0 * 132 + c0]       = acc[mi][ni][0];
                Cs[r0 * 132 + c0 + 1]   = acc[mi][ni][1];
                Cs[(r0 + 8) * 132 + c0]     = acc[mi][ni][2];
                Cs[(r0 + 8) * 132 + c0 + 1] = acc[mi][ni][3];
            }
        __syncthreads();
        uint32* dh = (uint32*)g_hh;
        const size_t rowbase = (size_t)es * CAP + row0;
#pragma unroll 4
        for (int it = 0; it < 32; it++) {
            int idx = tid + it * 256;
            int r = idx >> 6, cp = idx & 63;
            float v0 = gelu_f(Cs[r * 132 + cp * 2]     + bias_s[cp * 2]);
            float v1 = gelu_f(Cs[r * 132 + cp * 2 + 1] + bias_s[cp * 2 + 1]);
            dh[(rowbase + r) * 512 + (col0 >> 1) + cp] = packf2(v0, v1);
        }
    } else {
        float wv[8];
#pragma unroll
        for (int mi = 0; mi < 4; mi++) {
            wv[mi * 2]     = g_w[e * CAP + row0 + warpM * 64 + mi * 16 + (lane >> 2)];
            wv[mi * 2 + 1] = g_w[e * CAP + row0 + warpM * 64 + mi * 16 + (lane >> 2) + 8];
        }
#pragma unroll
        for (int mi = 0; mi < 4; mi++)
#pragma unroll
            for (int ni = 0; ni < 4; ni++) {
                int r0 = warpM * 64 + mi * 16 + (lane >> 2);
                int c0 = warpN * 32 + ni * 8 + (lane & 3) * 2;
                Cs[r0 * 132 + c0]       = (acc[mi][ni][0] + bias_s[c0])     * wv[mi * 2];
                Cs[r0 * 132 + c0 + 1]   = (acc[mi][ni][1] + bias_s[c0 + 1]) * wv[mi * 2];
                Cs[(r0 + 8) * 132 + c0]     = (acc[mi][ni][2] + bias_s[c0])     * wv[mi * 2 + 1];
                Cs[(r0 + 8) * 132 + c0 + 1] = (acc[mi][ni][3] + bias_s[c0 + 1]) * wv[mi * 2 + 1];
            }
        __syncthreads();
        FENCE_ASYNC();
        if (tid < 128) {
            const int r = tid;
            const int tok = g_idx[e * CAP + row0 + r];
            float* gdst = out + (size_t)tok * D_DIM + s * K_DIM + col0;
            uint32 sa = sb + (uint32)r * 132 * 4;
            asm volatile(
                "cp.reduce.async.bulk.global.shared::cta.bulk_group.add.f32 [%0], [%1], %2;"
                :: "l"(gdst), "r"(sa), "r"(512u) : "memory");
            asm volatile("cp.async.bulk.commit_group;" ::: "memory");
            asm volatile("cp.async.bulk.wait_group 0;" ::: "memory");
        }
        __syncthreads();
    }
}

// ------------------------------ launch -------------------------------------
extern "C" void kernel_launch(void* const* d_in, const int* in_sizes, int n_in,
                              void* d_out, int out_size) {
    const float* x  = (const float*)d_in[0];
    const float* Wr = (const float*)d_in[1];
    const float* W1 = (const float*)d_in[2];
    const float* b1 = (const float*)d_in[3];
    const float* W2 = (const float*)d_in[4];
    const float* b2 = (const float*)d_in[5];
    float* out = (float*)d_out;

    cudaFuncSetAttribute(moe_mma<false>, cudaFuncAttributeMaxDynamicSharedMemorySize,
                         SMEM_GEMM);
    cudaFuncSetAttribute(moe_mma<true>, cudaFuncAttributeMaxDynamicSharedMemorySize,
                         SMEM_GEMM);

    const int n4 = out_size / 4;
    zero_kernel<<<(n4 + 255) / 256, 256>>>((float4*)out, n4);
    router_kernel<<<T_TOK / 128, 256>>>(x, Wr);
    topk_kernel<<<E_EXP, 256>>>();
    gather_kernel<<<E_EXP * CAP, 256>>>(x);
    moe_mma<false><<<dim3(8, 4, E_EXP * S_SHARD), 256, SMEM_GEMM>>>(W1, b1, nullptr);
    moe_mma<true><<<dim3(2, 4, E_EXP * S_SHARD), 256, SMEM_GEMM>>>(W2, b2, out);
}